// round 2
// baseline (speedup 1.0000x reference)
#include <cuda_runtime.h>

// Problem constants
#define Bb 2
#define Hh 8
#define NCC 32
#define CC 64
#define OO 2
#define DD 128
#define BH (Bb*Hh)              // 16
#define NTILES (BH*NCC)         // 512
#define TILE_STRIDE (CC*OO*DD)  // 16384
#define OUT_ELEMS (NTILES*TILE_STRIDE) // 8388608

// Per-chunk recurrent states h0 used by each tile: states[bh*NC+n][128][128]
__device__ float g_states[NTILES * DD * DD];   // 33.5 MB static scratch

// ---------------------------------------------------------------------------
// Chain kernel: 16 blocks (one per (b,h)), sequential over 32 chunks.
// Only position c=63 matters for the state recurrence. With O=2:
//   uv0 = u0 - w0^T H
//   uv1 = u1 - a0 .* (w1^T H) - (w1.w0) * uv0
//   H'  = H .* (a0.*a1)[e] + w0[d]*(uv0.*a1)[e] + w1[d]*uv1[e]
// then rowwise-norm gelu activation (unless linear_activation).
// ---------------------------------------------------------------------------
__global__ __launch_bounds__(256) void chain_kernel(
    const float* __restrict__ q, const float* __restrict__ w,
    const float* __restrict__ u, const float* __restrict__ a,
    const float* __restrict__ init, const int* __restrict__ linflag,
    float* __restrict__ dout)
{
    extern __shared__ float sm[];
    float* Hs    = sm;                 // 128 * 129 (padded pitch)
    float* vw0   = Hs + 128*129;       // 128
    float* vw1   = vw0 + 128;
    float* vu0   = vw1 + 128;
    float* vu1   = vu0 + 128;
    float* va0   = vu1 + 128;
    float* va1   = va0 + 128;
    float* kth   = va1 + 128;          // 2*128
    float* coefA = kth + 256;          // 128
    float* coefB = coefA + 128;        // 128
    float* coefC = coefB + 128;        // 128
    float* norms = coefC + 128;        // 128
    float* ssww  = norms + 128;        // 1

    const int t  = threadIdx.x;
    const int bh = blockIdx.x;
    const int lin = *linflag;

    // Load initial state
    const float* ip = init + bh * (DD*DD);
    for (int k = t; k < DD*DD; k += 256)
        Hs[(k >> 7) * 129 + (k & 127)] = ip[k];
    __syncthreads();

    for (int n = 0; n < NCC; n++) {
        // Publish h0 for this chunk's output tile
        float* sp = g_states + (bh * NCC + n) * (DD*DD);
        for (int k = t; k < DD*DD; k += 256)
            sp[k] = Hs[(k >> 7) * 129 + (k & 127)];

        // Load the c=63 vectors for both orders
        int base = ((bh * NCC + n) * CC + (CC - 1)) * (OO * DD);
        if (t < 128) {
            vw0[t] = w[base + t];        vw1[t] = w[base + DD + t];
            vu0[t] = u[base + t];        vu1[t] = u[base + DD + t];
            va0[t] = a[base + t];        va1[t] = a[base + DD + t];
        }
        __syncthreads();

        // scalar w1 . w0 (warp 0)
        if (t < 32) {
            float s = 0.f;
            #pragma unroll
            for (int i = 0; i < 4; i++) s += vw0[t + 32*i] * vw1[t + 32*i];
            #pragma unroll
            for (int o = 16; o; o >>= 1) s += __shfl_xor_sync(0xffffffffu, s, o);
            if (t == 0) *ssww = s;
        }
        __syncthreads();

        // kth0[e] = w0^T H, kth1[e] = w1^T H
        {
            const int e = t & 127, g = t >> 7;
            const float* wv = g ? vw1 : vw0;
            float acc = 0.f;
            #pragma unroll 8
            for (int d = 0; d < DD; d++)
                acc = fmaf(wv[d], Hs[d*129 + e], acc);
            kth[g*128 + e] = acc;
        }
        __syncthreads();

        if (t < 128) {
            float sww = *ssww;
            float uv0 = vu0[t] - kth[t];
            float uv1 = vu1[t] - va0[t]*kth[128 + t] - sww*uv0;
            coefA[t] = va0[t] * va1[t];
            coefB[t] = uv0 * va1[t];
            coefC[t] = uv1;
        }
        __syncthreads();

        // State update (fused over both orders)
        {
            const int e = t & 127, g = t >> 7;
            const float cA = coefA[e], cB = coefB[e], cC = coefC[e];
            #pragma unroll 4
            for (int d = g*64; d < g*64 + 64; d++) {
                float h = Hs[d*129 + e];
                Hs[d*129 + e] = fmaf(h, cA, fmaf(vw0[d], cB, vw1[d]*cC));
            }
        }
        __syncthreads();

        if (!lin) {
            // Row norms over e
            if (t < 128) {
                float s = 0.f;
                #pragma unroll 8
                for (int e = 0; e < 128; e++) { float v = Hs[t*129 + e]; s = fmaf(v, v, s); }
                norms[t] = sqrtf(s) + 1e-6f;
            }
            __syncthreads();
            // h = x/2 * gelu_tanh(2x/n) = 0.25*x*z*(1+tanh(0.79788456*(z+0.044715 z^3)))
            {
                const int e = t & 127, g = t >> 7;
                for (int d = g*64; d < g*64 + 64; d++) {
                    float x = Hs[d*129 + e];
                    float z = 2.f * x / norms[d];
                    float inner = 0.7978845608028654f * fmaf(0.044715f*z*z, z, z);
                    float th = tanhf(inner);
                    Hs[d*129 + e] = 0.25f * x * z * (1.f + th);
                }
            }
            __syncthreads();
        }
    }

    // h_final goes after the main output block
    float* hf = dout + OUT_ELEMS + bh * (DD*DD);
    for (int k = t; k < DD*DD; k += 256)
        hf[k] = Hs[(k >> 7) * 129 + (k & 127)];
}

// ---------------------------------------------------------------------------
// Output kernel: one block per (b,h,n) tile (512 blocks).
// Computes M = X * H where X rows = {q0,w0,q1,w1} x 64 positions (256x128),
// H = h0 (128x128). Then elementwise epilogue produces out0/out1.
// ---------------------------------------------------------------------------
#define XPITCH 257
__global__ __launch_bounds__(256, 1) void out_kernel(
    const float* __restrict__ q, const float* __restrict__ w,
    const float* __restrict__ u, const float* __restrict__ a,
    float* __restrict__ out)
{
    extern __shared__ float sm[];
    float* XsT   = sm;                       // 128 * 257 (K-major transposed X)
    float* Hs    = XsT + 128*XPITCH;         // 128 * 128
    float* partw = Hs + 128*128;             // 256
    float* partq = partw + 256;              // 256
    float* sww   = partq + 256;              // 64
    float* sqw   = sww + 64;                 // 64

    const int t = threadIdx.x;
    const int tile = blockIdx.x;
    const int base = tile * TILE_STRIDE;

    // Load H (h0 for this chunk)
    const float* hp = g_states + tile * (DD*DD);
    for (int k = t; k < DD*DD; k += 256) Hs[k] = hp[k];

    // Load X transposed: row r = type*64 + c, types {0:q0, 1:w0, 2:q1, 3:w1}
    #pragma unroll
    for (int v = 0; v < 4; v++) {
        const float* src = (v & 1) ? w : q;
        const int s = v >> 1;
        for (int k = t; k < CC*DD; k += 256) {
            int c = k >> 7, d = k & 127;
            XsT[d*XPITCH + v*64 + c] = src[base + c*(OO*DD) + s*DD + d];
        }
    }
    __syncthreads();

    // Per-position scalars w1.w0 and q1.w0
    {
        const int c = t >> 2, p = t & 3;
        float pw = 0.f, pq = 0.f;
        #pragma unroll 8
        for (int i = 0; i < 32; i++) {
            int d = p*32 + i;
            float w0v = XsT[d*XPITCH + 64 + c];
            pw = fmaf(XsT[d*XPITCH + 192 + c], w0v, pw);
            pq = fmaf(XsT[d*XPITCH + 128 + c], w0v, pq);
        }
        partw[t] = pw; partq[t] = pq;
    }
    __syncthreads();
    if (t < 64) {
        sww[t] = partw[t*4] + partw[t*4+1] + partw[t*4+2] + partw[t*4+3];
        sqw[t] = partq[t*4] + partq[t*4+1] + partq[t*4+2] + partq[t*4+3];
    }
    __syncthreads();

    // Register-blocked GEMM: thread (tr, tc) computes rows {tr+32i}, cols {16tc+j}
    const int tr = t & 31, tc = t >> 5;
    float acc[8][16];
    #pragma unroll
    for (int i = 0; i < 8; i++)
        #pragma unroll
        for (int j = 0; j < 16; j++) acc[i][j] = 0.f;

    #pragma unroll 2
    for (int d = 0; d < DD; d++) {
        float av[8];
        #pragma unroll
        for (int i = 0; i < 8; i++) av[i] = XsT[d*XPITCH + tr + 32*i];
        float bv[16];
        #pragma unroll
        for (int jb = 0; jb < 4; jb++) {
            float4 bb = *(const float4*)&Hs[d*DD + tc*16 + jb*4];
            bv[jb*4+0] = bb.x; bv[jb*4+1] = bb.y; bv[jb*4+2] = bb.z; bv[jb*4+3] = bb.w;
        }
        #pragma unroll
        for (int i = 0; i < 8; i++)
            #pragma unroll
            for (int j = 0; j < 16; j++)
                acc[i][j] = fmaf(av[i], bv[j], acc[i][j]);
    }

    // Epilogue: row r = tr+32i  ->  type = i>>1, cpair = i&1, c = tr + 32*(i&1)
    // i = type*2 + cp: Aq0=acc[cp], Aw0=acc[2+cp], Aq1=acc[4+cp], Aw1=acc[6+cp]
    const int e0 = tc * 16;
    #pragma unroll
    for (int cp = 0; cp < 2; cp++) {
        const int c = tr + 32*cp;
        const int cb = base + c*(OO*DD);
        const float cw = sww[c], cq = sqw[c];
        #pragma unroll
        for (int jb = 0; jb < 4; jb++) {
            float4 t4;
            t4 = *(const float4*)&q[cb + e0 + jb*4];       float q0v[4] = {t4.x,t4.y,t4.z,t4.w};
            t4 = *(const float4*)&u[cb + e0 + jb*4];       float u0v[4] = {t4.x,t4.y,t4.z,t4.w};
            t4 = *(const float4*)&a[cb + e0 + jb*4];       float a0v[4] = {t4.x,t4.y,t4.z,t4.w};
            t4 = *(const float4*)&q[cb + DD + e0 + jb*4];  float q1v[4] = {t4.x,t4.y,t4.z,t4.w};
            t4 = *(const float4*)&u[cb + DD + e0 + jb*4];  float u1v[4] = {t4.x,t4.y,t4.z,t4.w};
            float o0[4], o1[4];
            #pragma unroll
            for (int jj = 0; jj < 4; jj++) {
                const int j = jb*4 + jj;
                float uv0  = u0v[jj] - acc[2+cp][j];
                float out0 = fmaf(q0v[jj], uv0, acc[0+cp][j]);
                float kth1 = fmaf(cw, uv0, a0v[jj]*acc[6+cp][j]);
                float uv1  = u1v[jj] - kth1;
                float oi1  = fmaf(cq, uv0, a0v[jj]*acc[4+cp][j]);
                float out1 = fmaf(q1v[jj], uv1, oi1);
                o0[jj] = out0; o1[jj] = out1;
            }
            *(float4*)&out[cb + e0 + jb*4]      = make_float4(o0[0],o0[1],o0[2],o0[3]);
            *(float4*)&out[cb + DD + e0 + jb*4] = make_float4(o1[0],o1[1],o1[2],o1[3]);
        }
    }
}

// ---------------------------------------------------------------------------

#define CHAIN_SMEM_BYTES ((128*129 + 6*128 + 256 + 3*128 + 128 + 8) * 4)
#define OUT_SMEM_BYTES   ((128*XPITCH + 128*128 + 256 + 256 + 64 + 64) * 4)

extern "C" void kernel_launch(void* const* d_in, const int* in_sizes, int n_in,
                              void* d_out, int out_size) {
    const float* q    = (const float*)d_in[0];
    const float* w    = (const float*)d_in[1];
    const float* u    = (const float*)d_in[2];
    const float* a    = (const float*)d_in[3];
    const float* init = (const float*)d_in[4];
    const int*   lin  = (const int*)d_in[5];
    float* out = (float*)d_out;

    cudaFuncSetAttribute(chain_kernel, cudaFuncAttributeMaxDynamicSharedMemorySize, CHAIN_SMEM_BYTES);
    cudaFuncSetAttribute(out_kernel,   cudaFuncAttributeMaxDynamicSharedMemorySize, OUT_SMEM_BYTES);

    chain_kernel<<<BH, 256, CHAIN_SMEM_BYTES>>>(q, w, u, a, init, lin, out);
    out_kernel<<<NTILES, 256, OUT_SMEM_BYTES>>>(q, w, u, a, out);
}

// round 3
// speedup vs baseline: 1.4767x; 1.4767x over previous
#include <cuda_runtime.h>

// Problem constants
#define Bb 2
#define Hh 8
#define NCC 32
#define CC 64
#define OO 2
#define DD 128
#define BH (Bb*Hh)              // 16
#define NTILES (BH*NCC)         // 512
#define TILE_STRIDE (CC*OO*DD)  // 16384
#define OUT_ELEMS (NTILES*TILE_STRIDE) // 8388608

// Per-chunk recurrent states h0 used by each tile: states[bh*NC+n][128][128]
__device__ float g_states[NTILES * DD * DD];   // 33.5 MB static scratch

// ---------------------------------------------------------------------------
// Chain kernel: 16 blocks (one per (b,h)), 1024 threads, sequential over 32
// chunks. Only position c=63 matters for the recurrence. With O=2:
//   uv0 = u0 - w0^T H
//   uv1 = u1 - a0 .* (w1^T H) - (w1.w0) * uv0
//   H'  = H .* (a0.*a1)[e] + w0[d]*(uv0.*a1)[e] + w1[d]*uv1[e]
// then rowwise-norm gelu activation (unless linear_activation).
// ---------------------------------------------------------------------------
__global__ __launch_bounds__(1024) void chain_kernel(
    const float* __restrict__ q, const float* __restrict__ w,
    const float* __restrict__ u, const float* __restrict__ a,
    const float* __restrict__ init, const int* __restrict__ linflag,
    float* __restrict__ dout)
{
    extern __shared__ float sm[];
    float* Hs    = sm;                 // 128 * 129 (padded pitch)
    float* V     = Hs + 128*129;       // 6 * 128: w0,w1,u0,u1,a0,a1
    float* kth   = V + 6*128;          // 2*128
    float* coefA = kth + 256;          // 128
    float* coefB = coefA + 128;        // 128
    float* coefC = coefB + 128;        // 128
    float* rn    = coefC + 128;        // 128 (2/norm per row)
    float* ssww  = rn + 128;           // 1

    const int t  = threadIdx.x;        // 0..1023
    const int bh = blockIdx.x;
    const int lin = *linflag;

    float* vw0 = V;        float* vw1 = V + 128;
    float* vu0 = V + 256;  float* vu1 = V + 384;
    float* va0 = V + 512;  float* va1 = V + 640;

    // Load initial state
    const float* ip = init + bh * (DD*DD);
    for (int k = t; k < DD*DD; k += 1024)
        Hs[(k >> 7) * 129 + (k & 127)] = ip[k];
    __syncthreads();

    for (int n = 0; n < NCC; n++) {
        // Publish h0 for this chunk's output tile + load c=63 vectors
        float* sp = g_states + (bh * NCC + n) * (DD*DD);
        for (int k = t; k < DD*DD; k += 1024)
            sp[k] = Hs[(k >> 7) * 129 + (k & 127)];

        const int base = ((bh * NCC + n) * CC + (CC - 1)) * (OO * DD);
        if (t < 768) {
            const int v = t >> 7, d = t & 127;
            const float* src = (v < 2) ? w : ((v < 4) ? u : a);
            V[v*128 + d] = src[base + (v & 1) * DD + d];
        }
        __syncthreads();

        // warp 0: scalar w1 . w0 ; everyone: kth (4 threads per output)
        if (t < 32) {
            float s = 0.f;
            #pragma unroll
            for (int i = 0; i < 4; i++) s += vw0[t + 32*i] * vw1[t + 32*i];
            #pragma unroll
            for (int o = 16; o; o >>= 1) s += __shfl_xor_sync(0xffffffffu, s, o);
            if (t == 0) *ssww = s;
        }
        {
            const int o = t >> 2, p = t & 3;
            const int g = o >> 7, e = o & 127;
            const float* wv = g ? vw1 : vw0;
            float acc = 0.f;
            #pragma unroll 8
            for (int i = 0; i < 32; i++) {
                const int d = p + 4*i;
                acc = fmaf(wv[d], Hs[d*129 + e], acc);
            }
            acc += __shfl_xor_sync(0xffffffffu, acc, 1);
            acc += __shfl_xor_sync(0xffffffffu, acc, 2);
            if (p == 0) kth[o] = acc;
        }
        __syncthreads();

        if (t < 128) {
            const float sww = *ssww;
            const float uv0 = vu0[t] - kth[t];
            const float uv1 = vu1[t] - va0[t]*kth[128 + t] - sww*uv0;
            coefA[t] = va0[t] * va1[t];
            coefB[t] = uv0 * va1[t];
            coefC[t] = uv1;
        }
        __syncthreads();

        // State update (both orders fused): 16 elems/thread, e fixed per thread
        {
            const int e = t & 127, d0 = t >> 7;
            const float cA = coefA[e], cB = coefB[e], cC = coefC[e];
            #pragma unroll
            for (int i = 0; i < 16; i++) {
                const int d = d0 + 8*i;
                float h = Hs[d*129 + e];
                Hs[d*129 + e] = fmaf(h, cA, fmaf(vw0[d], cB, vw1[d]*cC));
            }
        }
        __syncthreads();

        if (!lin) {
            // Row norms over e: 8 threads per row
            {
                const int r = t >> 3, p = t & 7;
                float s = 0.f;
                #pragma unroll
                for (int i = 0; i < 16; i++) {
                    float v = Hs[r*129 + p + 8*i];
                    s = fmaf(v, v, s);
                }
                s += __shfl_xor_sync(0xffffffffu, s, 1);
                s += __shfl_xor_sync(0xffffffffu, s, 2);
                s += __shfl_xor_sync(0xffffffffu, s, 4);
                if (p == 0) rn[r] = __fdividef(2.f, sqrtf(s) + 1e-6f);
            }
            __syncthreads();
            // h = 0.25*x*z*(1+tanh(inner)), z = 2x/n
            //   = 0.5*x*z*ex/(ex+1), ex = exp(2*inner)
            {
                const int e = t & 127, d0 = t >> 7;
                #pragma unroll
                for (int i = 0; i < 16; i++) {
                    const int d = d0 + 8*i;
                    float x = Hs[d*129 + e];
                    float z = x * rn[d];
                    float inner = 0.7978845608028654f * fmaf(0.044715f*z*z, z, z);
                    float ex = __expf(fminf(2.f*inner, 80.f));
                    Hs[d*129 + e] = 0.5f * x * z * __fdividef(ex, ex + 1.f);
                }
            }
            __syncthreads();
        }
    }

    // h_final goes after the main output block
    float* hf = dout + OUT_ELEMS + bh * (DD*DD);
    for (int k = t; k < DD*DD; k += 1024)
        hf[k] = Hs[(k >> 7) * 129 + (k & 127)];
}

// ---------------------------------------------------------------------------
// Output kernel: one block (512 threads) per (b,h,n) tile (512 blocks).
// Computes M = X * H where X rows = {q0,w0,q1,w1} x 64 positions (256x128),
// H = h0 (128x128). Then elementwise epilogue produces out0/out1.
// ---------------------------------------------------------------------------
#define XPITCH 257
__global__ __launch_bounds__(512, 1) void out_kernel(
    const float* __restrict__ q, const float* __restrict__ w,
    const float* __restrict__ u, const float* __restrict__ a,
    float* __restrict__ out)
{
    extern __shared__ float sm[];
    float* XsT   = sm;                       // 128 * 257 (K-major transposed X)
    float* Hs    = XsT + 128*XPITCH;         // 128 * 128
    float* partw = Hs + 128*128;             // 512
    float* partq = partw + 512;              // 512
    float* sww   = partq + 512;              // 64
    float* sqw   = sww + 64;                 // 64

    const int t = threadIdx.x;               // 0..511
    const int tile = blockIdx.x;
    const int base = tile * TILE_STRIDE;

    // Load H (h0 for this chunk)
    const float* hp = g_states + tile * (DD*DD);
    for (int k = t; k < DD*DD; k += 512) Hs[k] = hp[k];

    // Load X transposed: row r = type*64 + c, types {0:q0, 1:w0, 2:q1, 3:w1}
    #pragma unroll
    for (int v = 0; v < 4; v++) {
        const float* src = (v & 1) ? w : q;
        const int s = v >> 1;
        for (int k = t; k < CC*DD; k += 512) {
            int c = k >> 7, d = k & 127;
            XsT[d*XPITCH + v*64 + c] = src[base + c*(OO*DD) + s*DD + d];
        }
    }
    __syncthreads();

    // Per-position scalars w1.w0 and q1.w0 (8 partners per position)
    {
        const int c = t >> 3, p = t & 7;
        float pw = 0.f, pq = 0.f;
        #pragma unroll 8
        for (int i = 0; i < 16; i++) {
            int d = p*16 + i;
            float w0v = XsT[d*XPITCH + 64 + c];
            pw = fmaf(XsT[d*XPITCH + 192 + c], w0v, pw);
            pq = fmaf(XsT[d*XPITCH + 128 + c], w0v, pq);
        }
        partw[t] = pw; partq[t] = pq;
    }
    __syncthreads();
    if (t < 64) {
        float sw = 0.f, sq = 0.f;
        #pragma unroll
        for (int p = 0; p < 8; p++) { sw += partw[t*8 + p]; sq += partq[t*8 + p]; }
        sww[t] = sw; sqw[t] = sq;
    }
    __syncthreads();

    // Register-blocked GEMM: thread (tr, tc) -> rows {tr+32i}, cols {8tc..8tc+7}
    const int tr = t & 31, tc = t >> 5;      // tc 0..15
    const int e0 = tc * 8;
    float acc[8][8];
    #pragma unroll
    for (int i = 0; i < 8; i++)
        #pragma unroll
        for (int j = 0; j < 8; j++) acc[i][j] = 0.f;

    #pragma unroll 4
    for (int d = 0; d < DD; d++) {
        float av[8];
        #pragma unroll
        for (int i = 0; i < 8; i++) av[i] = XsT[d*XPITCH + tr + 32*i];
        float bv[8];
        #pragma unroll
        for (int jb = 0; jb < 2; jb++) {
            float4 bb = *(const float4*)&Hs[d*DD + e0 + jb*4];
            bv[jb*4+0] = bb.x; bv[jb*4+1] = bb.y; bv[jb*4+2] = bb.z; bv[jb*4+3] = bb.w;
        }
        #pragma unroll
        for (int i = 0; i < 8; i++)
            #pragma unroll
            for (int j = 0; j < 8; j++)
                acc[i][j] = fmaf(av[i], bv[j], acc[i][j]);
    }

    // Epilogue: row r = tr+32i, i = type*2 + cp  ->  c = tr + 32*cp
    // Aq0=acc[cp], Aw0=acc[2+cp], Aq1=acc[4+cp], Aw1=acc[6+cp]
    #pragma unroll
    for (int cp = 0; cp < 2; cp++) {
        const int c = tr + 32*cp;
        const int cb = base + c*(OO*DD);
        const float cw = sww[c], cq = sqw[c];
        #pragma unroll
        for (int jb = 0; jb < 2; jb++) {
            const int eo = e0 + jb*4;
            float4 t4;
            t4 = *(const float4*)&q[cb + eo];       float q0v[4] = {t4.x,t4.y,t4.z,t4.w};
            t4 = *(const float4*)&u[cb + eo];       float u0v[4] = {t4.x,t4.y,t4.z,t4.w};
            t4 = *(const float4*)&a[cb + eo];       float a0v[4] = {t4.x,t4.y,t4.z,t4.w};
            t4 = *(const float4*)&q[cb + DD + eo];  float q1v[4] = {t4.x,t4.y,t4.z,t4.w};
            t4 = *(const float4*)&u[cb + DD + eo];  float u1v[4] = {t4.x,t4.y,t4.z,t4.w};
            float o0[4], o1[4];
            #pragma unroll
            for (int jj = 0; jj < 4; jj++) {
                const int j = jb*4 + jj;
                float uv0  = u0v[jj] - acc[2+cp][j];
                float out0 = fmaf(q0v[jj], uv0, acc[0+cp][j]);
                float kth1 = fmaf(cw, uv0, a0v[jj]*acc[6+cp][j]);
                float uv1  = u1v[jj] - kth1;
                float oi1  = fmaf(cq, uv0, a0v[jj]*acc[4+cp][j]);
                float out1 = fmaf(q1v[jj], uv1, oi1);
                o0[jj] = out0; o1[jj] = out1;
            }
            *(float4*)&out[cb + eo]      = make_float4(o0[0],o0[1],o0[2],o0[3]);
            *(float4*)&out[cb + DD + eo] = make_float4(o1[0],o1[1],o1[2],o1[3]);
        }
    }
}

// ---------------------------------------------------------------------------

#define CHAIN_SMEM_BYTES ((128*129 + 6*128 + 256 + 3*128 + 128 + 8) * 4)
#define OUT_SMEM_BYTES   ((128*XPITCH + 128*128 + 512 + 512 + 64 + 64) * 4)

extern "C" void kernel_launch(void* const* d_in, const int* in_sizes, int n_in,
                              void* d_out, int out_size) {
    const float* q    = (const float*)d_in[0];
    const float* w    = (const float*)d_in[1];
    const float* u    = (const float*)d_in[2];
    const float* a    = (const float*)d_in[3];
    const float* init = (const float*)d_in[4];
    const int*   lin  = (const int*)d_in[5];
    float* out = (float*)d_out;

    cudaFuncSetAttribute(chain_kernel, cudaFuncAttributeMaxDynamicSharedMemorySize, CHAIN_SMEM_BYTES);
    cudaFuncSetAttribute(out_kernel,   cudaFuncAttributeMaxDynamicSharedMemorySize, OUT_SMEM_BYTES);

    chain_kernel<<<BH, 1024, CHAIN_SMEM_BYTES>>>(q, w, u, a, init, lin, out);
    out_kernel<<<NTILES, 512, OUT_SMEM_BYTES>>>(q, w, u, a, out);
}

// round 4
// speedup vs baseline: 2.6498x; 1.7945x over previous
#include <cuda_runtime.h>

// Problem constants
#define Bb 2
#define Hh 8
#define NCC 32
#define CC 64
#define OO 2
#define DD 128
#define BH (Bb*Hh)              // 16
#define NTILES (BH*NCC)         // 512
#define TILE_STRIDE (CC*OO*DD)  // 16384
#define OUT_ELEMS (NTILES*TILE_STRIDE) // 8388608

// Per-chunk recurrent states h0: states[bh*NC+n][128][128] (d-major)
__device__ float g_states[NTILES * DD * DD];   // 33.5 MB static scratch
__device__ int   g_ready[NTILES];              // producer->consumer flags

#define XP 257
#define OUT_SMEM_FLOATS (128*XP + 64 + 64)
#define SMEM_BYTES (OUT_SMEM_FLOATS * 4)

__global__ __launch_bounds__(1024, 1) void fused_kernel(
    const float* __restrict__ q, const float* __restrict__ w,
    const float* __restrict__ u, const float* __restrict__ a,
    const float* __restrict__ init, const int* __restrict__ linflag,
    float* __restrict__ dout)
{
    extern __shared__ float sm[];
    const int t = threadIdx.x;
    const int b = blockIdx.x;

    if (b < BH) {
        // ================= CHAIN ROLE (blocks 0..15, wave-1 resident) ======
        float* Hs   = sm;               // 128*129
        float* V    = Hs + 128*129;     // 6*128: w0,w1,u0,u1,a0,a1
        float* kth  = V + 768;          // 2*128
        float* rn   = kth + 256;        // 128
        float* ssww = rn + 128;         // 1
        float* vw0 = V;        float* vw1 = V + 128;
        float* vu0 = V + 256;  float* vu1 = V + 384;
        float* va0 = V + 512;  float* va1 = V + 640;

        const int bh = b;
        const int lin = *linflag;

        // Preamble: init state -> smem + publish chunk-0 state
        const float* ip  = init + bh * (DD*DD);
        float* sp0 = g_states + (bh * NCC) * (DD*DD);
        for (int k = t; k < DD*DD; k += 1024) {
            float v = ip[k];
            Hs[(k >> 7) * 129 + (k & 127)] = v;
            sp0[k] = v;
        }
        __syncthreads();
        if (t == 0) { __threadfence(); atomicExch(&g_ready[bh*NCC], 1); }

        for (int n = 0; n < NCC; n++) {
            // Load c=63 vectors for both orders
            const int base = ((bh * NCC + n) * CC + (CC - 1)) * (OO * DD);
            if (t < 768) {
                const int v = t >> 7, d = t & 127;
                const float* src = (v < 2) ? w : ((v < 4) ? u : a);
                V[v*128 + d] = src[base + (v & 1) * DD + d];
            }
            __syncthreads();

            // warp0: sww = w1.w0 ; all: kth0/kth1 in one H pass
            if (t < 32) {
                float s = 0.f;
                #pragma unroll
                for (int i = 0; i < 4; i++) s += vw0[t + 32*i] * vw1[t + 32*i];
                #pragma unroll
                for (int o = 16; o; o >>= 1) s += __shfl_xor_sync(0xffffffffu, s, o);
                if (t == 0) *ssww = s;
            }
            {
                const int p = t & 7, e = t >> 3;       // 128 e x 8 partners
                float s0 = 0.f, s1 = 0.f;
                #pragma unroll
                for (int i = 0; i < 16; i++) {
                    const int d = p + 8*i;
                    const float h = Hs[d*129 + e];
                    s0 = fmaf(vw0[d], h, s0);
                    s1 = fmaf(vw1[d], h, s1);
                }
                s0 += __shfl_xor_sync(0xffffffffu, s0, 1);
                s0 += __shfl_xor_sync(0xffffffffu, s0, 2);
                s0 += __shfl_xor_sync(0xffffffffu, s0, 4);
                s1 += __shfl_xor_sync(0xffffffffu, s1, 1);
                s1 += __shfl_xor_sync(0xffffffffu, s1, 2);
                s1 += __shfl_xor_sync(0xffffffffu, s1, 4);
                if (p == 0) { kth[e] = s0; kth[128 + e] = s1; }
            }
            __syncthreads();

            // Update (coef inlined): H' = cA*H + cB*w0[d] + cC*w1[d]
            {
                const int e = t & 127, d0 = t >> 7;
                const float sww = *ssww;
                const float uv0 = vu0[e] - kth[e];
                const float uv1 = vu1[e] - va0[e]*kth[128 + e] - sww*uv0;
                const float cA = va0[e] * va1[e];
                const float cB = uv0 * va1[e];
                const float cC = uv1;
                #pragma unroll
                for (int i = 0; i < 16; i++) {
                    const int d = d0 + 8*i;
                    float h = Hs[d*129 + e];
                    Hs[d*129 + e] = fmaf(h, cA, fmaf(vw0[d], cB, vw1[d]*cC));
                }
            }
            __syncthreads();

            // Publish destination: next chunk's h0, or h_final after last chunk
            float* dst = (n < NCC-1) ? (g_states + (bh*NCC + n + 1) * (DD*DD))
                                     : (dout + OUT_ELEMS + bh * (DD*DD));

            if (!lin) {
                // Row norms (per d over e): 8 partners/row
                {
                    const int r = t >> 3, p = t & 7;
                    float s = 0.f;
                    #pragma unroll
                    for (int i = 0; i < 16; i++) {
                        float v = Hs[r*129 + p + 8*i];
                        s = fmaf(v, v, s);
                    }
                    s += __shfl_xor_sync(0xffffffffu, s, 1);
                    s += __shfl_xor_sync(0xffffffffu, s, 2);
                    s += __shfl_xor_sync(0xffffffffu, s, 4);
                    if (p == 0) rn[r] = __fdividef(2.f, sqrtf(s) + 1e-6f);
                }
                __syncthreads();
                // gelu + publish fused. |z|<=2 so no overflow guard needed.
                // 0.25*x*z*(1+tanh(i)) = 0.5*x*z/(1+exp(-2i))
                {
                    const int e = t & 127, d0 = t >> 7;
                    #pragma unroll
                    for (int i = 0; i < 16; i++) {
                        const int d = d0 + 8*i;
                        float x = Hs[d*129 + e];
                        float z = x * rn[d];
                        float inner = 0.7978845608028654f * fmaf(0.044715f*z*z, z, z);
                        float ex = __expf(-2.f * inner);
                        float val = __fdividef(0.5f * x * z, 1.f + ex);
                        Hs[d*129 + e] = val;
                        dst[d*128 + e] = val;
                    }
                }
            } else {
                const int e = t & 127, d0 = t >> 7;
                #pragma unroll
                for (int i = 0; i < 16; i++) {
                    const int d = d0 + 8*i;
                    dst[d*128 + e] = Hs[d*129 + e];
                }
            }
            __syncthreads();
            if (t == 0 && n < NCC-1) {
                __threadfence(); atomicExch(&g_ready[bh*NCC + n + 1], 1);
            }
        }
    } else {
        // ================= OUT ROLE (blocks 16..527) =======================
        const int j  = b - BH;
        const int n  = j >> 4, bh = j & 15;      // chunk-major -> early chunks first
        const int tile = bh * NCC + n;
        const int base = tile * TILE_STRIDE;

        float* XsT = sm;                         // 128 x 257, rows r=type*64+c
        float* sww = XsT + 128*XP;               // 64
        float* sqw = sww + 64;                   // 64

        // Acquire this chunk's state
        if (t == 0) {
            long long spins = 0;
            while (atomicAdd(&g_ready[tile], 0) == 0) {
                __nanosleep(64);
                if (++spins > (1LL << 31)) break;   // safety, never hit
            }
            __threadfence();
        }
        __syncthreads();

        // Load X^T: types {0:q0, 1:w0, 2:q1, 3:w1}
        for (int k = t; k < 4*CC*DD; k += 1024) {
            const int v = k >> 13, rem = k & 8191;
            const int c = rem >> 7, d = rem & 127;
            const float* src = (v & 1) ? w : q;
            XsT[d*XP + v*64 + c] = src[base + c*(OO*DD) + (v >> 1)*DD + d];
        }
        __syncthreads();

        // Per-position scalars w1.w0 / q1.w0 (16 partners per c)
        {
            const int c = t >> 4, p = t & 15;
            float pw = 0.f, pq = 0.f;
            #pragma unroll
            for (int i = 0; i < 8; i++) {
                const int d = p*8 + i;
                const float w0v = XsT[d*XP + 64 + c];
                pw = fmaf(XsT[d*XP + 192 + c], w0v, pw);
                pq = fmaf(XsT[d*XP + 128 + c], w0v, pq);
            }
            pw += __shfl_xor_sync(0xffffffffu, pw, 1);
            pw += __shfl_xor_sync(0xffffffffu, pw, 2);
            pw += __shfl_xor_sync(0xffffffffu, pw, 4);
            pw += __shfl_xor_sync(0xffffffffu, pw, 8);
            pq += __shfl_xor_sync(0xffffffffu, pq, 1);
            pq += __shfl_xor_sync(0xffffffffu, pq, 2);
            pq += __shfl_xor_sync(0xffffffffu, pq, 4);
            pq += __shfl_xor_sync(0xffffffffu, pq, 8);
            if (p == 0) { sww[c] = pw; sqw[c] = pq; }
        }
        __syncthreads();

        // GEMM: thread (tr=c, tcg) -> 4 types x 8 e-cols. H from L1/L2.
        const int tr = t & 63, tcg = t >> 6;
        const int e0 = tcg * 8;
        const float* Hp = g_states + tile * (DD*DD) + e0;

        float acc[4][8];
        #pragma unroll
        for (int v = 0; v < 4; v++)
            #pragma unroll
            for (int jj = 0; jj < 8; jj++) acc[v][jj] = 0.f;

        #pragma unroll 2
        for (int d = 0; d < DD; d++) {
            float av[4];
            #pragma unroll
            for (int v = 0; v < 4; v++) av[v] = XsT[d*XP + v*64 + tr];
            const float4 b0 = *(const float4*)(Hp + d*DD);
            const float4 b1 = *(const float4*)(Hp + d*DD + 4);
            const float bv[8] = {b0.x,b0.y,b0.z,b0.w,b1.x,b1.y,b1.z,b1.w};
            #pragma unroll
            for (int v = 0; v < 4; v++)
                #pragma unroll
                for (int jj = 0; jj < 8; jj++)
                    acc[v][jj] = fmaf(av[v], bv[jj], acc[v][jj]);
        }

        // Epilogue for (c=tr, e0..e0+7)
        {
            const int cb = base + tr*(OO*DD) + e0;
            const float cw = sww[tr], cq = sqw[tr];
            #pragma unroll
            for (int jb = 0; jb < 2; jb++) {
                const int eo = jb*4;
                float4 t4;
                t4 = *(const float4*)&q[cb + eo];       float q0v[4] = {t4.x,t4.y,t4.z,t4.w};
                t4 = *(const float4*)&u[cb + eo];       float u0v[4] = {t4.x,t4.y,t4.z,t4.w};
                t4 = *(const float4*)&a[cb + eo];       float a0v[4] = {t4.x,t4.y,t4.z,t4.w};
                t4 = *(const float4*)&q[cb + DD + eo];  float q1v[4] = {t4.x,t4.y,t4.z,t4.w};
                t4 = *(const float4*)&u[cb + DD + eo];  float u1v[4] = {t4.x,t4.y,t4.z,t4.w};
                float o0[4], o1[4];
                #pragma unroll
                for (int jj = 0; jj < 4; jj++) {
                    const int e = eo + jj;
                    float uv0  = u0v[jj] - acc[1][e];
                    float out0 = fmaf(q0v[jj], uv0, acc[0][e]);
                    float kth1 = fmaf(cw, uv0, a0v[jj]*acc[3][e]);
                    float uv1  = u1v[jj] - kth1;
                    float oi1  = fmaf(cq, uv0, a0v[jj]*acc[2][e]);
                    float out1 = fmaf(q1v[jj], uv1, oi1);
                    o0[jj] = out0; o1[jj] = out1;
                }
                *(float4*)&dout[cb + eo]      = make_float4(o0[0],o0[1],o0[2],o0[3]);
                *(float4*)&dout[cb + DD + eo] = make_float4(o1[0],o1[1],o1[2],o1[3]);
            }
        }
    }
}

// ---------------------------------------------------------------------------

extern "C" void kernel_launch(void* const* d_in, const int* in_sizes, int n_in,
                              void* d_out, int out_size) {
    const float* q    = (const float*)d_in[0];
    const float* w    = (const float*)d_in[1];
    const float* u    = (const float*)d_in[2];
    const float* a    = (const float*)d_in[3];
    const float* init = (const float*)d_in[4];
    const int*   lin  = (const int*)d_in[5];
    float* out = (float*)d_out;

    // Reset producer->consumer flags every launch (graph-capturable memset)
    void* flagptr = nullptr;
    cudaGetSymbolAddress(&flagptr, g_ready);
    cudaMemsetAsync(flagptr, 0, NTILES * sizeof(int));

    cudaFuncSetAttribute(fused_kernel, cudaFuncAttributeMaxDynamicSharedMemorySize, SMEM_BYTES);
    fused_kernel<<<BH + NTILES, 1024, SMEM_BYTES>>>(q, w, u, a, init, lin, out);
}